// round 11
// baseline (speedup 1.0000x reference)
#include <cuda_runtime.h>
#include <math_constants.h>

#define NROWS 2048
#define DIM   1024
#define KCENT 256
#define NMID  288            // midpoints padded with +inf
#define NPAIR 272            // pairs[j] = (mid[j], mid[j+1]), j <= 271
#define NB    2048
#define TPB   256

__device__ unsigned char g_luti8[NB];   // per-bin lower-bound index (<= 255)
__device__ float2        g_pairs[NPAIR];
__device__ float         g_scen[KCENT];
__device__ float         g_sb[2];       // scale, bias

// -------- prep: 8 CTAs build the LUT (no atomics, no scan) --------
__global__ __launch_bounds__(TPB)
void prep_kernel(const float* __restrict__ centroids) {
    __shared__ float smidp[NMID];
    __shared__ int   sbin[KCENT];

    const int t = threadIdx.x;

    const float c0 = centroids[t];
    const float c1 = centroids[t < KCENT - 1 ? t + 1 : KCENT - 1];
    const float mid = (t < KCENT - 1) ? 0.5f * (c0 + c1) : CUDART_INF_F;
    smidp[t] = mid;
    if (t < NMID - KCENT) smidp[KCENT + t] = CUDART_INF_F;
    __syncthreads();

    const float lo    = smidp[0];
    const float hi    = smidp[KCENT - 2];
    const float scale = (float)NB / fmaxf(hi - lo, 1e-30f);
    const float bias  = -lo * scale;

    if (blockIdx.x == 0) {
        g_scen[t] = c0;
        if (t < NPAIR) g_pairs[t] = make_float2(smidp[t], smidp[t + 1]);
        if (t == 0) { g_sb[0] = scale; g_sb[1] = bias; }
    }

    // bins of midpoints (sorted since bin() monotone); sentinel at t = 255
    int mybin = 0x7fffffff;
    if (t < KCENT - 1) {
        float bf = fmaf(mid, scale, bias);
        mybin = (int)fminf(fmaxf(bf, 0.0f), (float)(NB - 1));
    }
    sbin[t] = mybin;
    __syncthreads();

    // luti8[b] = #{m : bin(m) < b} via 8-step branchless lower bound (<= 255)
    const int b = blockIdx.x * TPB + t;
    int pos = 0;
    #pragma unroll
    for (int s = 128; s; s >>= 1) {
        int np = pos + s;
        if (sbin[np - 1] < b) pos = np;
    }
    g_luti8[b] = (unsigned char)pos;
}

// -------- main: 2 rows/CTA, fused norms, depth-3 quantizer --------
__global__ __launch_bounds__(TPB)
void planar_quant_kernel(const float* __restrict__ x,
                         const float* __restrict__ rot2,
                         float* __restrict__ out_xhat,
                         float* __restrict__ out_idx,
                         int write_idx) {
    __shared__ unsigned char luti8[NB];     // 2 KB
    __shared__ float2        pairs[NPAIR];  // 2.1 KB
    __shared__ float         scen[KCENT];   // 1 KB
    __shared__ float         sred[2][8];

    const int t    = threadIdx.x;
    const int lane = t & 31;
    const int wid  = t >> 5;
    const int rowA = blockIdx.x * 2;
    const int rowB = rowA + 1;

    // ---- long-latency loads first ----
    const float4 xvA = reinterpret_cast<const float4*>(x + (size_t)rowA * DIM)[t];
    const float4 xvB = reinterpret_cast<const float4*>(x + (size_t)rowB * DIM)[t];
    const float4 rv  = reinterpret_cast<const float4*>(rot2)[t];
    const float scale = g_sb[0];
    const float bias  = g_sb[1];

    // ---- table copy (coalesced): luti8 8B/thr, pairs 136 f4, scen 64 f4 ----
    reinterpret_cast<uint2*>(luti8)[t] = reinterpret_cast<const uint2*>(g_luti8)[t];
    if (t < NPAIR / 2)
        reinterpret_cast<float4*>(pairs)[t] = reinterpret_cast<const float4*>(g_pairs)[t];
    if (t < KCENT / 4)
        reinterpret_cast<float4*>(scen)[t]  = reinterpret_cast<const float4*>(g_scen)[t];

    // ---- norm partials for both rows (shuffle-only) ----
    float ssA = xvA.x * xvA.x + xvA.y * xvA.y + xvA.z * xvA.z + xvA.w * xvA.w;
    float ssB = xvB.x * xvB.x + xvB.y * xvB.y + xvB.z * xvB.z + xvB.w * xvB.w;
    #pragma unroll
    for (int o = 16; o; o >>= 1) {
        ssA += __shfl_xor_sync(0xffffffffu, ssA, o);
        ssB += __shfl_xor_sync(0xffffffffu, ssB, o);
    }
    if (lane == 0) { sred[0][wid] = ssA; sred[1][wid] = ssB; }

    __syncthreads();   // single barrier: tables + partials

    float4 a0 = reinterpret_cast<float4*>(sred[0])[0];
    float4 a1 = reinterpret_cast<float4*>(sred[0])[1];
    float4 b0 = reinterpret_cast<float4*>(sred[1])[0];
    float4 b1 = reinterpret_cast<float4*>(sred[1])[1];
    const float normA = fmaxf(sqrtf((a0.x + a0.y) + (a0.z + a0.w) +
                                    (a1.x + a1.y) + (a1.z + a1.w)), 1e-8f);
    const float normB = fmaxf(sqrtf((b0.x + b0.y) + (b0.z + b0.w) +
                                    (b1.x + b1.y) + (b1.z + b1.w)), 1e-8f);
    const float rnA = 1.0f / normA;
    const float rnB = 1.0f / normB;

    // depth-3 quant: LDS.U8 -> 3 independent LDS.64 probes -> payload
    auto quant = [&](float v, int& idx, float& q) {
        float bf = fmaf(v, scale, bias);
        int b = (int)fminf(fmaxf(bf, 0.0f), (float)(NB - 1));
        int i = (int)luti8[b];
        float2 p0 = pairs[i];       // mid[i],   mid[i+1]
        float2 p1 = pairs[i + 2];   // mid[i+2], mid[i+3]
        float2 p2 = pairs[i + 4];   // mid[i+4], mid[i+5]
        i += (p0.x < v) + (p0.y < v) + (p1.x < v) +
             (p1.y < v) + (p2.x < v) + (p2.y < v);
        idx = i;
        q = scen[i];
    };

    #pragma unroll
    for (int r = 0; r < 2; r++) {
        const float4 xv  = r ? xvB : xvA;
        const float  rn  = r ? rnB : rnA;
        const float  nrm = r ? normB : normA;
        const int    row = r ? rowB : rowA;

        const float v0 = xv.x * rn, v1 = xv.y * rn;
        const float v2 = xv.z * rn, v3 = xv.w * rn;
        const float r0 = rv.x * v0 - rv.y * v1;
        const float r1 = rv.y * v0 + rv.x * v1;
        const float r2 = rv.z * v2 - rv.w * v3;
        const float r3 = rv.w * v2 + rv.z * v3;

        int   i0, i1, i2, i3;
        float q0, q1, q2, q3;
        quant(r0, i0, q0);
        quant(r1, i1, q1);
        quant(r2, i2, q2);
        quant(r3, i3, q3);

        float4 xh;
        xh.x = ( rv.x * q0 + rv.y * q1) * nrm;
        xh.y = (-rv.y * q0 + rv.x * q1) * nrm;
        xh.z = ( rv.z * q2 + rv.w * q3) * nrm;
        xh.w = (-rv.w * q2 + rv.z * q3) * nrm;
        reinterpret_cast<float4*>(out_xhat + (size_t)row * DIM)[t] = xh;

        if (write_idx) {
            float4 fi;
            fi.x = (float)i0; fi.y = (float)i1; fi.z = (float)i2; fi.w = (float)i3;
            reinterpret_cast<float4*>(out_idx + (size_t)row * DIM)[t] = fi;
        }
    }
}

extern "C" void kernel_launch(void* const* d_in, const int* in_sizes, int n_in,
                              void* d_out, int out_size) {
    const float* x         = (const float*)d_in[0];  // [2048, 1024]
    const float* centroids = (const float*)d_in[1];  // [256]
    const float* rot2      = (const float*)d_in[2];  // [512, 2]

    float* out = (float*)d_out;
    const int full = (out_size >= 2 * NROWS * DIM);
    float* out_xhat = out;
    float* out_idx  = full ? out + (size_t)NROWS * DIM : out;

    prep_kernel<<<NB / TPB, TPB>>>(centroids);
    planar_quant_kernel<<<NROWS / 2, TPB>>>(x, rot2, out_xhat, out_idx, full);
}

// round 12
// speedup vs baseline: 1.2031x; 1.2031x over previous
#include <cuda_runtime.h>
#include <math_constants.h>

#define NROWS 2048
#define DIM   1024
#define KCENT 256
#define NMID  288            // midpoints padded with +inf
#define NPAIR 272            // pairs[j] = (mid[j], mid[j+1])
#define NB    4096
#define TPB   256
#define LUTCTAS (NB / TPB)   // 16

__device__ unsigned char g_luti8[NB];   // per-bin lower-bound index (<= 255)
__device__ float2        g_pairs[NPAIR];
__device__ float         g_scen[KCENT];
__device__ float         g_sb[2];       // scale, bias
__device__ float         g_norm[NROWS];

// -------- launch 1: LUT build (CTAs 0..15) + norms (CTAs 16..271) --------
__global__ __launch_bounds__(TPB)
void prep_norm_kernel(const float* __restrict__ x,
                      const float* __restrict__ centroids) {
    const int t = threadIdx.x;

    if (blockIdx.x < LUTCTAS) {
        __shared__ float smidp[NMID];
        __shared__ int   sbin[KCENT];

        const float c0 = centroids[t];
        const float c1 = centroids[t < KCENT - 1 ? t + 1 : KCENT - 1];
        const float mid = (t < KCENT - 1) ? 0.5f * (c0 + c1) : CUDART_INF_F;
        smidp[t] = mid;
        if (t < NMID - KCENT) smidp[KCENT + t] = CUDART_INF_F;
        __syncthreads();

        const float lo    = smidp[0];
        const float hi    = smidp[KCENT - 2];
        const float scale = (float)NB / fmaxf(hi - lo, 1e-30f);
        const float bias  = -lo * scale;

        if (blockIdx.x == 0) {
            g_scen[t] = c0;
            for (int j = t; j < NPAIR; j += TPB)
                g_pairs[j] = make_float2(smidp[j], smidp[j + 1]);
            if (t == 0) { g_sb[0] = scale; g_sb[1] = bias; }
        }

        // bins of midpoints (sorted since bin() monotone); sentinel at t = 255
        int mybin = 0x7fffffff;
        if (t < KCENT - 1) {
            float bf = fmaf(mid, scale, bias);
            mybin = (int)fminf(fmaxf(bf, 0.0f), (float)(NB - 1));
        }
        sbin[t] = mybin;
        __syncthreads();

        // luti8[b] = #{m : bin(m) < b} via 8-step branchless lower bound
        const int b = blockIdx.x * TPB + t;
        int pos = 0;
        #pragma unroll
        for (int s = 128; s; s >>= 1) {
            int np = pos + s;
            if (sbin[np - 1] < b) pos = np;
        }
        g_luti8[b] = (unsigned char)pos;
    } else {
        // norms: warp per row, 8 rows/CTA
        const int lane = t & 31;
        const int row  = (blockIdx.x - LUTCTAS) * 8 + (t >> 5);
        const float4* __restrict__ xr =
            reinterpret_cast<const float4*>(x) + (size_t)row * (DIM / 4);

        float ss = 0.f;
        #pragma unroll
        for (int k = 0; k < 8; k++) {
            float4 v = xr[k * 32 + lane];
            ss += v.x * v.x + v.y * v.y + v.z * v.z + v.w * v.w;
        }
        #pragma unroll
        for (int o = 16; o; o >>= 1) ss += __shfl_xor_sync(0xffffffffu, ss, o);
        if (lane == 0) g_norm[row] = fmaxf(sqrtf(ss), 1e-8f);
    }
}

// -------- launch 2: 2 rows/CTA, no reduction, one barrier, grouped quant --------
__global__ __launch_bounds__(TPB)
void planar_quant_kernel(const float* __restrict__ x,
                         const float* __restrict__ rot2,
                         float* __restrict__ out_xhat,
                         float* __restrict__ out_idx,
                         int write_idx) {
    __shared__ unsigned char luti8[NB];     // 4 KB
    __shared__ float2        pairs[NPAIR];  // 2.1 KB
    __shared__ float         scen[KCENT];   // 1 KB

    const int t    = threadIdx.x;
    const int rowA = blockIdx.x * 2;
    const int rowB = rowA + 1;

    // ---- long-latency loads first ----
    const float4 xvA = reinterpret_cast<const float4*>(x + (size_t)rowA * DIM)[t];
    const float4 xvB = reinterpret_cast<const float4*>(x + (size_t)rowB * DIM)[t];
    const float4 rv  = reinterpret_cast<const float4*>(rot2)[t];
    const float normA = g_norm[rowA];
    const float normB = g_norm[rowB];
    const float scale = g_sb[0];
    const float bias  = g_sb[1];

    // ---- table copy (coalesced): luti8 = 1 uint4/thr, pairs 136 f4, scen 64 f4 ----
    reinterpret_cast<uint4*>(luti8)[t] = reinterpret_cast<const uint4*>(g_luti8)[t];
    if (t < NPAIR / 2)
        reinterpret_cast<float4*>(pairs)[t] = reinterpret_cast<const float4*>(g_pairs)[t];
    if (t < KCENT / 4)
        reinterpret_cast<float4*>(scen)[t]  = reinterpret_cast<const float4*>(g_scen)[t];

    __syncthreads();   // single barrier: table visibility

    const float rnA = 1.0f / normA;
    const float rnB = 1.0f / normB;

    // ---- rotate all 8 scalars into an array ----
    float vq[8];
    {
        const float a0 = xvA.x * rnA, a1 = xvA.y * rnA;
        const float a2 = xvA.z * rnA, a3 = xvA.w * rnA;
        vq[0] = rv.x * a0 - rv.y * a1;
        vq[1] = rv.y * a0 + rv.x * a1;
        vq[2] = rv.z * a2 - rv.w * a3;
        vq[3] = rv.w * a2 + rv.z * a3;
        const float b0 = xvB.x * rnB, b1 = xvB.y * rnB;
        const float b2 = xvB.z * rnB, b3 = xvB.w * rnB;
        vq[4] = rv.x * b0 - rv.y * b1;
        vq[5] = rv.y * b0 + rv.x * b1;
        vq[6] = rv.z * b2 - rv.w * b3;
        vq[7] = rv.w * b2 + rv.z * b3;
    }

    // ---- grouped quantize: 8 LDS.U8, then 16 LDS.64, then 8 payload LDS ----
    int idx[8];
    #pragma unroll
    for (int j = 0; j < 8; j++) {
        float bf = fmaf(vq[j], scale, bias);
        int b = (int)fminf(fmaxf(bf, 0.0f), (float)(NB - 1));
        idx[j] = (int)luti8[b];
    }
    #pragma unroll
    for (int j = 0; j < 8; j++) {
        const float v = vq[j];
        float2 p0 = pairs[idx[j]];
        float2 p1 = pairs[idx[j] + 2];
        idx[j] += (p0.x < v) + (p0.y < v) + (p1.x < v) + (p1.y < v);
    }
    float qv[8];
    #pragma unroll
    for (int j = 0; j < 8; j++) qv[j] = scen[idx[j]];

    // ---- inverse rotate, rescale, store ----
    float4 xh;
    xh.x = ( rv.x * qv[0] + rv.y * qv[1]) * normA;
    xh.y = (-rv.y * qv[0] + rv.x * qv[1]) * normA;
    xh.z = ( rv.z * qv[2] + rv.w * qv[3]) * normA;
    xh.w = (-rv.w * qv[2] + rv.z * qv[3]) * normA;
    reinterpret_cast<float4*>(out_xhat + (size_t)rowA * DIM)[t] = xh;

    float4 xh2;
    xh2.x = ( rv.x * qv[4] + rv.y * qv[5]) * normB;
    xh2.y = (-rv.y * qv[4] + rv.x * qv[5]) * normB;
    xh2.z = ( rv.z * qv[6] + rv.w * qv[7]) * normB;
    xh2.w = (-rv.w * qv[6] + rv.z * qv[7]) * normB;
    reinterpret_cast<float4*>(out_xhat + (size_t)rowB * DIM)[t] = xh2;

    if (write_idx) {
        float4 fiA, fiB;
        fiA.x = (float)idx[0]; fiA.y = (float)idx[1];
        fiA.z = (float)idx[2]; fiA.w = (float)idx[3];
        fiB.x = (float)idx[4]; fiB.y = (float)idx[5];
        fiB.z = (float)idx[6]; fiB.w = (float)idx[7];
        reinterpret_cast<float4*>(out_idx + (size_t)rowA * DIM)[t] = fiA;
        reinterpret_cast<float4*>(out_idx + (size_t)rowB * DIM)[t] = fiB;
    }
}

extern "C" void kernel_launch(void* const* d_in, const int* in_sizes, int n_in,
                              void* d_out, int out_size) {
    const float* x         = (const float*)d_in[0];  // [2048, 1024]
    const float* centroids = (const float*)d_in[1];  // [256]
    const float* rot2      = (const float*)d_in[2];  // [512, 2]

    float* out = (float*)d_out;
    const int full = (out_size >= 2 * NROWS * DIM);
    float* out_xhat = out;
    float* out_idx  = full ? out + (size_t)NROWS * DIM : out;

    prep_norm_kernel<<<LUTCTAS + NROWS / 8, TPB>>>(x, centroids);
    planar_quant_kernel<<<NROWS / 2, TPB>>>(x, rot2, out_xhat, out_idx, full);
}